// round 2
// baseline (speedup 1.0000x reference)
#include <cuda_runtime.h>
#include <cstdint>

#define BATCH 8
#define SEQ 8192
#define DM 1024
#define BLOCKS_PER_B 32
#define ROWS_PER_BLOCK (SEQ / BLOCKS_PER_B)   // 256
#define TILE 16
#define NTILES (ROWS_PER_BLOCK / TILE)        // 16
#define THREADS 256
#define NPART (BATCH * BLOCKS_PER_B)          // 256

// scratch partials: acc[0..1023], m at [1024], l at [1025]
__device__ float g_part[NPART][DM + 8];

#define SMEM_FLOATS (2 * TILE * DM + 2 * TILE)

__device__ __forceinline__ void cp_async16(uint32_t s, const void* g) {
    asm volatile("cp.async.cg.shared.global [%0], [%1], 16;\n" :: "r"(s), "l"(g));
}

__global__ void __launch_bounds__(THREADS, 1) pool_partial(
    const float* __restrict__ x,
    const int* __restrict__ mask,          // jnp.bool_ promoted to int32 by harness
    const float* __restrict__ q)
{
    extern __shared__ float sm[];
    float* buf      = sm;                 // 2 * TILE * DM
    float* s_scores = sm + 2 * TILE * DM; // TILE
    float* s_w      = s_scores + TILE;    // TILE

    const int t    = threadIdx.x;
    const int lane = t & 31;
    const int warp = t >> 5;
    const int b    = blockIdx.x / BLOCKS_PER_B;
    const int blk  = blockIdx.x % BLOCKS_PER_B;
    const int row0 = blk * ROWS_PER_BLOCK;

    const float* xb = x + ((size_t)b * SEQ + row0) * DM;
    const int* mb = mask + (size_t)b * SEQ + row0;

    // query slice for the score phase: lane covers float4 indices lane + 32*j
    float4 qr[8];
#pragma unroll
    for (int j = 0; j < 8; j++)
        qr[j] = reinterpret_cast<const float4*>(q)[lane + 32 * j];

    float4 acc = make_float4(0.f, 0.f, 0.f, 0.f);
    float m = -1e30f, l = 0.f;

    uint32_t sbase = (uint32_t)__cvta_generic_to_shared(buf);

    // prefetch tile 0 into buffer 0
#pragma unroll
    for (int j = 0; j < 16; j++) {
        int idx = t + THREADS * j;   // float4 index within tile (4096 total)
        cp_async16(sbase + idx * 16, xb + idx * 4);
    }
    asm volatile("cp.async.commit_group;\n");

    for (int it = 0; it < NTILES; it++) {
        const int cur = it & 1;

        if (it + 1 < NTILES) {
            const float* src = xb + (size_t)(it + 1) * TILE * DM;
            uint32_t dst = sbase + ((it + 1) & 1) * (TILE * DM * 4);
#pragma unroll
            for (int j = 0; j < 16; j++) {
                int idx = t + THREADS * j;
                cp_async16(dst + idx * 16, src + idx * 4);
            }
            asm volatile("cp.async.commit_group;\n");
            asm volatile("cp.async.wait_group 1;\n");
        } else {
            asm volatile("cp.async.wait_group 0;\n");
        }
        __syncthreads();

        const float* tb = buf + cur * TILE * DM;

        // scores: warp w handles rows 2w, 2w+1 of the tile
#pragma unroll
        for (int rr = 0; rr < 2; rr++) {
            const int r = warp * 2 + rr;
            const float4* rowp = reinterpret_cast<const float4*>(tb + r * DM);
            float s = 0.f;
#pragma unroll
            for (int j = 0; j < 8; j++) {
                float4 v = rowp[lane + 32 * j];
                s += v.x * qr[j].x + v.y * qr[j].y + v.z * qr[j].z + v.w * qr[j].w;
            }
#pragma unroll
            for (int o = 16; o > 0; o >>= 1) s += __shfl_xor_sync(0xffffffffu, s, o);
            if (lane == 0) {
                const int grow = it * TILE + r;
                s *= 0.03125f;                 // 1/sqrt(1024)
                if (mb[grow]) s = -1e30f;      // padded
                s_scores[r] = s;
            }
        }
        __syncthreads();

        // running max update (all threads compute identically)
        float mt = m;
#pragma unroll
        for (int r = 0; r < TILE; r++) mt = fmaxf(mt, s_scores[r]);
        const float factor = __expf(m - mt);
        if (t < TILE) s_w[t] = __expf(s_scores[t] - mt);
        __syncthreads();

        float lsum = 0.f;
#pragma unroll
        for (int r = 0; r < TILE; r++) lsum += s_w[r];
        l = l * factor + lsum;
        acc.x *= factor; acc.y *= factor; acc.z *= factor; acc.w *= factor;
        m = mt;

        // accumulate: thread t owns columns [4t, 4t+4)
        const float4* colp = reinterpret_cast<const float4*>(tb) + t;
#pragma unroll
        for (int r = 0; r < TILE; r++) {
            const float w = s_w[r];
            float4 v = colp[r * (DM / 4)];
            acc.x += w * v.x; acc.y += w * v.y; acc.z += w * v.z; acc.w += w * v.w;
        }
        __syncthreads();   // protect smem buffer + s_scores/s_w reuse
    }

    float* gp = g_part[blockIdx.x];
    reinterpret_cast<float4*>(gp)[t] = acc;
    if (t == 0) { gp[DM] = m; gp[DM + 1] = l; }
}

__global__ void __launch_bounds__(THREADS) pool_combine(float* __restrict__ out)
{
    const int b = blockIdx.x;
    const int t = threadIdx.x;

    float M = -1e30f;
#pragma unroll
    for (int p = 0; p < BLOCKS_PER_B; p++)
        M = fmaxf(M, g_part[b * BLOCKS_PER_B + p][DM]);

    float4 o = make_float4(0.f, 0.f, 0.f, 0.f);
    float L = 0.f;
#pragma unroll 4
    for (int p = 0; p < BLOCKS_PER_B; p++) {
        const float* gp = g_part[b * BLOCKS_PER_B + p];
        const float w = __expf(gp[DM] - M);
        L += w * gp[DM + 1];
        float4 a = reinterpret_cast<const float4*>(gp)[t];
        o.x += w * a.x; o.y += w * a.y; o.z += w * a.z; o.w += w * a.w;
    }
    const float inv = 1.f / L;
    reinterpret_cast<float4*>(out + (size_t)b * DM)[t] =
        make_float4(o.x * inv, o.y * inv, o.z * inv, o.w * inv);
}

extern "C" void kernel_launch(void* const* d_in, const int* in_sizes, int n_in,
                              void* d_out, int out_size)
{
    const float* x = (const float*)d_in[0];
    const int* mask = (const int*)d_in[1];
    const float* q = (const float*)d_in[2];
    float* out = (float*)d_out;

    const int smem = SMEM_FLOATS * sizeof(float);
    cudaFuncSetAttribute(pool_partial, cudaFuncAttributeMaxDynamicSharedMemorySize, smem);
    pool_partial<<<NPART, THREADS, smem>>>(x, mask, q);
    pool_combine<<<BATCH, THREADS>>>(out);
}

// round 3
// speedup vs baseline: 1.0334x; 1.0334x over previous
#include <cuda_runtime.h>
#include <cstdint>

#define BATCH 8
#define SEQ 8192
#define DM 1024
#define BLOCKS_PER_B 64
#define ROWS_PER_BLOCK (SEQ / BLOCKS_PER_B)   // 128
#define TILE 8
#define NTILES (ROWS_PER_BLOCK / TILE)        // 16
#define THREADS 256
#define NPART (BATCH * BLOCKS_PER_B)          // 512

// scratch partials: acc[0..1023], m at [1024], l at [1025]
__device__ float g_part[NPART][DM + 8];

#define SMEM_FLOATS (2 * TILE * DM + 2 * TILE)
#define TILE_F4 (TILE * DM / 4)               // 2048 float4 per tile
#define F4_PER_THREAD (TILE_F4 / THREADS)     // 8

__device__ __forceinline__ void cp_async16(uint32_t s, const void* g) {
    asm volatile("cp.async.cg.shared.global [%0], [%1], 16;\n" :: "r"(s), "l"(g));
}

__global__ void __launch_bounds__(THREADS) pool_partial(
    const float* __restrict__ x,
    const int* __restrict__ mask,          // jnp.bool_ promoted to int32 by harness
    const float* __restrict__ q)
{
    extern __shared__ float sm[];
    float* buf      = sm;                 // 2 * TILE * DM
    float* s_scores = sm + 2 * TILE * DM; // TILE
    float* s_w      = s_scores + TILE;    // TILE

    const int t    = threadIdx.x;
    const int lane = t & 31;
    const int warp = t >> 5;
    const int b    = blockIdx.x / BLOCKS_PER_B;
    const int blk  = blockIdx.x % BLOCKS_PER_B;
    const int row0 = blk * ROWS_PER_BLOCK;

    const float* xb = x + ((size_t)b * SEQ + row0) * DM;
    const int* mb = mask + (size_t)b * SEQ + row0;

    // query slice for the score phase: lane covers float4 indices lane + 32*j
    float4 qr[8];
#pragma unroll
    for (int j = 0; j < 8; j++)
        qr[j] = reinterpret_cast<const float4*>(q)[lane + 32 * j];

    float4 acc = make_float4(0.f, 0.f, 0.f, 0.f);
    float m = -1e30f, l = 0.f;

    uint32_t sbase = (uint32_t)__cvta_generic_to_shared(buf);

    // prefetch tile 0 into buffer 0
#pragma unroll
    for (int j = 0; j < F4_PER_THREAD; j++) {
        int idx = t + THREADS * j;
        cp_async16(sbase + idx * 16, xb + idx * 4);
    }
    asm volatile("cp.async.commit_group;\n");

    for (int it = 0; it < NTILES; it++) {
        const int cur = it & 1;

        if (it + 1 < NTILES) {
            const float* src = xb + (size_t)(it + 1) * TILE * DM;
            uint32_t dst = sbase + ((it + 1) & 1) * (TILE * DM * 4);
#pragma unroll
            for (int j = 0; j < F4_PER_THREAD; j++) {
                int idx = t + THREADS * j;
                cp_async16(dst + idx * 16, src + idx * 4);
            }
            asm volatile("cp.async.commit_group;\n");
            asm volatile("cp.async.wait_group 1;\n");
        } else {
            asm volatile("cp.async.wait_group 0;\n");
        }
        __syncthreads();

        const float* tb = buf + cur * TILE * DM;

        // scores: warp w handles row w of the tile (8 warps, 8 rows)
        {
            const int r = warp;
            const float4* rowp = reinterpret_cast<const float4*>(tb + r * DM);
            float s = 0.f;
#pragma unroll
            for (int j = 0; j < 8; j++) {
                float4 v = rowp[lane + 32 * j];
                s += v.x * qr[j].x + v.y * qr[j].y + v.z * qr[j].z + v.w * qr[j].w;
            }
#pragma unroll
            for (int o = 16; o > 0; o >>= 1) s += __shfl_xor_sync(0xffffffffu, s, o);
            if (lane == 0) {
                const int grow = it * TILE + r;
                s *= 0.03125f;                 // 1/sqrt(1024)
                if (mb[grow]) s = -1e30f;      // padded
                s_scores[r] = s;
            }
        }
        __syncthreads();

        // running max update (all threads compute identically)
        float mt = m;
#pragma unroll
        for (int r = 0; r < TILE; r++) mt = fmaxf(mt, s_scores[r]);
        const float factor = __expf(m - mt);
        if (t < TILE) s_w[t] = __expf(s_scores[t] - mt);
        __syncthreads();

        float lsum = 0.f;
#pragma unroll
        for (int r = 0; r < TILE; r++) lsum += s_w[r];
        l = l * factor + lsum;
        acc.x *= factor; acc.y *= factor; acc.z *= factor; acc.w *= factor;
        m = mt;

        // accumulate: thread t owns columns [4t, 4t+4)
        const float4* colp = reinterpret_cast<const float4*>(tb) + t;
#pragma unroll
        for (int r = 0; r < TILE; r++) {
            const float w = s_w[r];
            float4 v = colp[r * (DM / 4)];
            acc.x += w * v.x; acc.y += w * v.y; acc.z += w * v.z; acc.w += w * v.w;
        }
        __syncthreads();   // protect smem buffer + s_scores/s_w reuse
    }

    float* gp = g_part[blockIdx.x];
    reinterpret_cast<float4*>(gp)[t] = acc;
    if (t == 0) { gp[DM] = m; gp[DM + 1] = l; }
}

// grid = BATCH * 8 blocks, 128 threads; block handles 128 columns of one batch
#define CBLK 8
#define CTHREADS 128

__global__ void __launch_bounds__(CTHREADS) pool_combine(float* __restrict__ out)
{
    const int b = blockIdx.x / CBLK;
    const int c = blockIdx.x % CBLK;
    const int t = threadIdx.x;
    const int col = c * CTHREADS + t;

    float M = -1e30f;
#pragma unroll 8
    for (int p = 0; p < BLOCKS_PER_B; p++)
        M = fmaxf(M, g_part[b * BLOCKS_PER_B + p][DM]);

    float o = 0.f;
    float L = 0.f;
#pragma unroll 8
    for (int p = 0; p < BLOCKS_PER_B; p++) {
        const float* gp = g_part[b * BLOCKS_PER_B + p];
        const float w = __expf(gp[DM] - M);
        L += w * gp[DM + 1];
        o += w * gp[col];
    }
    out[(size_t)b * DM + col] = o / L;
}

extern "C" void kernel_launch(void* const* d_in, const int* in_sizes, int n_in,
                              void* d_out, int out_size)
{
    const float* x = (const float*)d_in[0];
    const int* mask = (const int*)d_in[1];
    const float* q = (const float*)d_in[2];
    float* out = (float*)d_out;

    const int smem = SMEM_FLOATS * sizeof(float);
    cudaFuncSetAttribute(pool_partial, cudaFuncAttributeMaxDynamicSharedMemorySize, smem);
    pool_partial<<<NPART, THREADS, smem>>>(x, mask, q);
    pool_combine<<<BATCH * CBLK, CTHREADS>>>(out);
}

// round 4
// speedup vs baseline: 1.2342x; 1.1943x over previous
#include <cuda_runtime.h>
#include <cstdint>

#define BATCH 8
#define SEQ 8192
#define DM 1024
#define TILE 8
#define THREADS 256
#define GRID 444                      // = 148 SMs * 3 resident blocks, single wave
#define TILES_PER_B (SEQ / TILE)      // 1024
#define MAXNB 56

// partials: acc[0..1023], m at [1024], l at [1025]
__device__ float g_part[GRID][DM + 8];
__device__ int g_cnt[BATCH];          // zero-initialized; reset by last block each launch

#define SMEM_FLOATS (2 * TILE * DM + TILE)
#define TILE_F4 (TILE * DM / 4)               // 2048
#define F4_PER_THREAD (TILE_F4 / THREADS)     // 8

__device__ __forceinline__ void cp_async16(uint32_t s, const void* g) {
    asm volatile("cp.async.cg.shared.global [%0], [%1], 16;\n" :: "r"(s), "l"(g));
}

__global__ void __launch_bounds__(THREADS) pool_fused(
    const float* __restrict__ x,
    const int* __restrict__ mask,          // jnp.bool_ promoted to int32
    const float* __restrict__ q,
    float* __restrict__ out)
{
    extern __shared__ float sm[];
    float* buf      = sm;                 // 2 * TILE * DM
    float* s_scores = sm + 2 * TILE * DM; // TILE

    const int t    = threadIdx.x;
    const int lane = t & 31;
    const int warp = t >> 5;

    // block -> (batch, slot) : batches 0-3 have 56 blocks, 4-7 have 55
    const int bid = blockIdx.x;
    int b, j, nb, pbase;
    if (bid < 224) { b = bid / 56;        j = bid - b * 56;         nb = 56; pbase = b * 56; }
    else { int r = bid - 224; b = 4 + r / 55; j = r - (b - 4) * 55; nb = 55; pbase = 224 + (b - 4) * 55; }

    // split 1024 tiles of this batch among nb blocks
    const int tb   = TILES_PER_B / nb;
    const int rem  = TILES_PER_B - tb * nb;
    const int ntiles = tb + (j < rem);
    const int tstart = j * tb + min(j, rem);
    const int row0   = tstart * TILE;

    const float* xb = x + ((size_t)b * SEQ + row0) * DM;
    const int*   mb = mask + (size_t)b * SEQ + row0;

    // query slice: lane covers float4 indices lane + 32*jj
    float4 qr[8];
#pragma unroll
    for (int jj = 0; jj < 8; jj++)
        qr[jj] = reinterpret_cast<const float4*>(q)[lane + 32 * jj];

    float4 acc = make_float4(0.f, 0.f, 0.f, 0.f);
    float m = -1e30f, l = 0.f;

    uint32_t sbase = (uint32_t)__cvta_generic_to_shared(buf);

    // prefetch tile 0 into buffer 0
#pragma unroll
    for (int jj = 0; jj < F4_PER_THREAD; jj++) {
        int idx = t + THREADS * jj;
        cp_async16(sbase + idx * 16, xb + idx * 4);
    }
    asm volatile("cp.async.commit_group;\n");

    for (int it = 0; it < ntiles; it++) {
        const int cur = it & 1;

        if (it + 1 < ntiles) {
            const float* src = xb + (size_t)(it + 1) * TILE * DM;
            uint32_t dst = sbase + ((it + 1) & 1) * (TILE * DM * 4);
#pragma unroll
            for (int jj = 0; jj < F4_PER_THREAD; jj++) {
                int idx = t + THREADS * jj;
                cp_async16(dst + idx * 16, src + idx * 4);
            }
            asm volatile("cp.async.commit_group;\n");
            asm volatile("cp.async.wait_group 1;\n");
        } else {
            asm volatile("cp.async.wait_group 0;\n");
        }
        __syncthreads();

        const float* tbuf = buf + cur * TILE * DM;

        // scores: warp w handles row w (8 warps, 8 rows)
        {
            const float4* rowp = reinterpret_cast<const float4*>(tbuf + warp * DM);
            float s = 0.f;
#pragma unroll
            for (int jj = 0; jj < 8; jj++) {
                float4 v = rowp[lane + 32 * jj];
                s += v.x * qr[jj].x + v.y * qr[jj].y + v.z * qr[jj].z + v.w * qr[jj].w;
            }
#pragma unroll
            for (int o = 16; o > 0; o >>= 1) s += __shfl_xor_sync(0xffffffffu, s, o);
            if (lane == 0) {
                s *= 0.03125f;                          // 1/sqrt(1024)
                if (mb[it * TILE + warp]) s = -1e30f;   // padded
                s_scores[warp] = s;
            }
        }
        __syncthreads();

        // online softmax update, weights computed redundantly per thread
        float sc[TILE];
#pragma unroll
        for (int r = 0; r < TILE; r++) sc[r] = s_scores[r];
        float mt = m;
#pragma unroll
        for (int r = 0; r < TILE; r++) mt = fmaxf(mt, sc[r]);
        const float factor = __expf(m - mt);
        float w[TILE], lsum = 0.f;
#pragma unroll
        for (int r = 0; r < TILE; r++) { w[r] = __expf(sc[r] - mt); lsum += w[r]; }
        l = l * factor + lsum;
        acc.x *= factor; acc.y *= factor; acc.z *= factor; acc.w *= factor;
        m = mt;

        // accumulate: thread t owns columns [4t, 4t+4)
        const float4* colp = reinterpret_cast<const float4*>(tbuf) + t;
#pragma unroll
        for (int r = 0; r < TILE; r++) {
            float4 v = colp[r * (DM / 4)];
            acc.x += w[r] * v.x; acc.y += w[r] * v.y; acc.z += w[r] * v.z; acc.w += w[r] * v.w;
        }
        __syncthreads();   // protect smem buffer + s_scores before reuse
    }

    // publish partial
    float* gp = g_part[bid];
    reinterpret_cast<float4*>(gp)[t] = acc;
    if (t == 0) { gp[DM] = m; gp[DM + 1] = l; }

    // last block of this batch combines (partials are L2-hot)
    __shared__ int s_last;
    __threadfence();
    __syncthreads();
    if (t == 0) s_last = (atomicAdd(&g_cnt[b], 1) == nb - 1);
    __syncthreads();
    if (!s_last) return;
    __threadfence();

    float M = -1e30f;
#pragma unroll 8
    for (int p = 0; p < MAXNB; p++) {
        if (p < nb) M = fmaxf(M, g_part[pbase + p][DM]);
    }

    float4 o = make_float4(0.f, 0.f, 0.f, 0.f);
    float L = 0.f;
#pragma unroll 4
    for (int p = 0; p < MAXNB; p++) {
        if (p < nb) {
            const float* pp = g_part[pbase + p];
            const float wgt = __expf(pp[DM] - M);
            L += wgt * pp[DM + 1];
            float4 a = reinterpret_cast<const float4*>(pp)[t];
            o.x += wgt * a.x; o.y += wgt * a.y; o.z += wgt * a.z; o.w += wgt * a.w;
        }
    }
    const float inv = 1.f / L;
    reinterpret_cast<float4*>(out + (size_t)b * DM)[t] =
        make_float4(o.x * inv, o.y * inv, o.z * inv, o.w * inv);

    if (t == 0) g_cnt[b] = 0;   // reset for next launch / graph replay
}

extern "C" void kernel_launch(void* const* d_in, const int* in_sizes, int n_in,
                              void* d_out, int out_size)
{
    const float* x = (const float*)d_in[0];
    const int* mask = (const int*)d_in[1];
    const float* q = (const float*)d_in[2];
    float* out = (float*)d_out;

    const int smem = SMEM_FLOATS * sizeof(float);
    cudaFuncSetAttribute(pool_fused, cudaFuncAttributeMaxDynamicSharedMemorySize, smem);
    pool_fused<<<GRID, THREADS, smem>>>(x, mask, q, out);
}

// round 5
// speedup vs baseline: 1.4280x; 1.1570x over previous
#include <cuda_runtime.h>
#include <cstdint>

#define BATCH 8
#define SEQ 8192
#define DM 1024
#define TILE 8
#define THREADS 256
#define BPB 37                        // blocks per batch
#define GRID (BATCH * BPB)            // 296 = 148 SMs * 2, single wave
#define TILES_PER_B (SEQ / TILE)      // 1024

// partials per block: acc[0..1023], m at [1024], l at [1025]
__device__ float g_part[GRID][DM + 8];
__device__ int g_cnt[BATCH];          // zeroed at load; reset by last block each launch

__global__ void __launch_bounds__(THREADS, 2) pool_fused(
    const float* __restrict__ x,
    const int* __restrict__ mask,     // jnp.bool_ promoted to int32
    const float* __restrict__ q,
    float* __restrict__ out)
{
    __shared__ float s_part[8][4];    // [warp][row-in-rowgroup] score partials
    __shared__ float s_w[9];          // 8 weights + factor
    __shared__ float4 s_red[256];     // final column-combine
    __shared__ int s_last;

    const int t    = threadIdx.x;
    const int lane = t & 31;
    const int warp = t >> 5;
    const int colg = t & 127;         // column group: owns cols [4*colg..+3] and [512+4*colg..+3]
    const int rowg = t >> 7;          // 0: rows 0-3 of tile, 1: rows 4-7

    // block -> (batch, slot): 37 blocks per batch
    const int bid = blockIdx.x;
    const int b = bid / BPB;
    const int j = bid - b * BPB;
    // split 1024 tiles among 37 blocks: first 25 get 28, rest 27
    const int tb  = TILES_PER_B / BPB;            // 27
    const int rem = TILES_PER_B - tb * BPB;       // 25
    const int ntiles = tb + (j < rem);
    const int tstart = j * tb + min(j, rem);

    const float* xb = x + ((size_t)b * SEQ + (size_t)tstart * TILE) * DM;
    const int*   mb = mask + (size_t)b * SEQ + (size_t)tstart * TILE;

    // query slice (8 regs)
    const float4 qa = reinterpret_cast<const float4*>(q)[colg];
    const float4 qb = reinterpret_cast<const float4*>(q)[128 + colg];

    float4 acc_a = make_float4(0.f, 0.f, 0.f, 0.f);
    float4 acc_b = make_float4(0.f, 0.f, 0.f, 0.f);
    float m = -1e30f, l = 0.f;

    // per-thread base pointer: row = rowg*4, col float4 index colg / 128+colg
    const float4* xp = reinterpret_cast<const float4*>(xb) + (size_t)(rowg * 4) * (DM / 4) + colg;

    float4 ca[4], cb[4], na[4], nb_[4];
    // load tile 0
#pragma unroll
    for (int rr = 0; rr < 4; rr++) {
        ca[rr] = xp[(size_t)rr * (DM / 4)];
        cb[rr] = xp[(size_t)rr * (DM / 4) + 128];
    }

    for (int it = 0; it < ntiles; it++) {
        // prefetch next tile (max slack)
        if (it + 1 < ntiles) {
            const float4* np = xp + (size_t)(it + 1) * TILE * (DM / 4);
#pragma unroll
            for (int rr = 0; rr < 4; rr++) {
                na[rr]  = np[(size_t)rr * (DM / 4)];
                nb_[rr] = np[(size_t)rr * (DM / 4) + 128];
            }
        }
        // warp0: fetch mask bits early
        int mrow = 0;
        if (warp == 0) mrow = mb[it * TILE + (lane & 7)];

        // column-partial scores: ps[rr] over this thread's 8 columns
        float ps[4];
#pragma unroll
        for (int rr = 0; rr < 4; rr++) {
            ps[rr] = ca[rr].x * qa.x + ca[rr].y * qa.y + ca[rr].z * qa.z + ca[rr].w * qa.w
                   + cb[rr].x * qb.x + cb[rr].y * qb.y + cb[rr].z * qb.z + cb[rr].w * qb.w;
        }
        // warp reduce (20 SHFL)
#pragma unroll
        for (int rr = 0; rr < 4; rr++) {
#pragma unroll
            for (int o = 16; o > 0; o >>= 1)
                ps[rr] += __shfl_xor_sync(0xffffffffu, ps[rr], o);
        }
        if (lane == 0) {
#pragma unroll
            for (int rr = 0; rr < 4; rr++) s_part[warp][rr] = ps[rr];
        }
        __syncthreads();

        // warp0 computes softmax update for the 8 rows
        if (warp == 0) {
            const int r  = lane & 7;
            const int rr = r & 3;
            const int wb = (r >> 2) << 2;   // rows 0-3 from warps 0-3, rows 4-7 from warps 4-7
            float sc = (s_part[wb][rr] + s_part[wb + 1][rr] + s_part[wb + 2][rr] + s_part[wb + 3][rr])
                       * 0.03125f;          // 1/sqrt(1024)
            const bool masked = (mrow != 0);
            float smax = masked ? -1e30f : sc;
#pragma unroll
            for (int o = 4; o > 0; o >>= 1)
                smax = fmaxf(smax, __shfl_xor_sync(0xffffffffu, smax, o));
            const float m_new  = fmaxf(m, smax);
            const float factor = __expf(m - m_new);
            const float w = masked ? 0.f : __expf(sc - m_new);
            float lsum = w;
#pragma unroll
            for (int o = 4; o > 0; o >>= 1)
                lsum += __shfl_xor_sync(0xffffffffu, lsum, o);
            l = l * factor + lsum;
            m = m_new;
            if (lane < 8) s_w[lane] = w;
            if (lane == 0) s_w[8] = factor;
        }
        __syncthreads();

        // rescale + accumulate from registers
        const float factor = s_w[8];
        acc_a.x *= factor; acc_a.y *= factor; acc_a.z *= factor; acc_a.w *= factor;
        acc_b.x *= factor; acc_b.y *= factor; acc_b.z *= factor; acc_b.w *= factor;
#pragma unroll
        for (int rr = 0; rr < 4; rr++) {
            const float w = s_w[rowg * 4 + rr];
            acc_a.x += w * ca[rr].x; acc_a.y += w * ca[rr].y;
            acc_a.z += w * ca[rr].z; acc_a.w += w * ca[rr].w;
            acc_b.x += w * cb[rr].x; acc_b.y += w * cb[rr].y;
            acc_b.z += w * cb[rr].z; acc_b.w += w * cb[rr].w;
        }
        // rotate buffers
#pragma unroll
        for (int rr = 0; rr < 4; rr++) { ca[rr] = na[rr]; cb[rr] = nb_[rr]; }
    }

    // combine the two row-groups (same columns) through smem, publish partial
    if (rowg == 0) {
        s_red[colg] = acc_a;
        s_red[128 + colg] = acc_b;
    }
    __syncthreads();
    float* gp = g_part[bid];
    if (rowg == 1) {
        float4 pa = s_red[colg];
        float4 pb = s_red[128 + colg];
        pa.x += acc_a.x; pa.y += acc_a.y; pa.z += acc_a.z; pa.w += acc_a.w;
        pb.x += acc_b.x; pb.y += acc_b.y; pb.z += acc_b.z; pb.w += acc_b.w;
        reinterpret_cast<float4*>(gp)[colg] = pa;
        reinterpret_cast<float4*>(gp)[128 + colg] = pb;
    }
    if (t == 0) { gp[DM] = m; gp[DM + 1] = l; }

    // last block of this batch combines (partials are L2-hot)
    __threadfence();
    __syncthreads();
    if (t == 0) s_last = (atomicAdd(&g_cnt[b], 1) == BPB - 1);
    __syncthreads();
    if (!s_last) return;
    __threadfence();

    const int pbase = b * BPB;
    float M = -1e30f;
#pragma unroll 8
    for (int p = 0; p < BPB; p++)
        M = fmaxf(M, g_part[pbase + p][DM]);

    float4 o = make_float4(0.f, 0.f, 0.f, 0.f);
    float L = 0.f;
#pragma unroll 4
    for (int p = 0; p < BPB; p++) {
        const float* pp = g_part[pbase + p];
        const float wgt = __expf(pp[DM] - M);
        L += wgt * pp[DM + 1];
        float4 a = reinterpret_cast<const float4*>(pp)[t];
        o.x += wgt * a.x; o.y += wgt * a.y; o.z += wgt * a.z; o.w += wgt * a.w;
    }
    const float inv = 1.f / L;
    reinterpret_cast<float4*>(out + (size_t)b * DM)[t] =
        make_float4(o.x * inv, o.y * inv, o.z * inv, o.w * inv);

    if (t == 0) g_cnt[b] = 0;   // reset for next launch / graph replay
}

extern "C" void kernel_launch(void* const* d_in, const int* in_sizes, int n_in,
                              void* d_out, int out_size)
{
    const float* x = (const float*)d_in[0];
    const int* mask = (const int*)d_in[1];
    const float* q = (const float*)d_in[2];
    float* out = (float*)d_out;

    pool_fused<<<GRID, THREADS>>>(x, mask, q, out);
}